// round 1
// baseline (speedup 1.0000x reference)
#include <cuda_runtime.h>

// ---------------------------------------------------------------------------
// SpatialWindowSelfAttention (Swin window MHSA), sm_103a
//   x:[B,65536,256]  -> qkv proj -> window attn (8x8 win, 8 heads, hd=32)
//   -> merge -> output proj -> out:[B,65536,256]
// Round 1: fp32 SIMT baseline. 3 kernels:
//   1) SGEMM  qkv = x @ Wqkv^T + b          (M=131072, N=768, K=256)
//   2) window attention (per window, per head)
//   3) SGEMM  out = y @ Wp^T + b            (M=131072, N=256, K=256)
// ---------------------------------------------------------------------------

#define C_DIM    256
#define QKV_DIM  768
#define N_HEADS  8
#define HEAD_DIM 32
#define IMG      256                 // h = w = 256 for this problem instance
#define TOKENS   (IMG * IMG)         // 65536
#define WS       64                  // 8x8 window
#define MAX_B    2

// scratch (allocation-free rule: __device__ globals)
__device__ float g_qkv[MAX_B * TOKENS * QKV_DIM];   // 402 MB
__device__ float g_y  [MAX_B * TOKENS * C_DIM];     // 134 MB

// ---------------------------------------------------------------------------
// SGEMM: C[M,N] = A[M,K] @ B[N,K]^T + bias[N]   (torch Linear convention)
// BM=BN=128, BK=16, 256 threads, 8x8 micro-tile. All dims divide evenly.
// ---------------------------------------------------------------------------
__global__ __launch_bounds__(256)
void sgemm_bias_kernel(const float* __restrict__ A,
                       const float* __restrict__ Bw,
                       const float* __restrict__ bias,
                       float* __restrict__ C,
                       int M, int N, int K)
{
    constexpr int BM = 128, BN = 128, BK = 16;
    __shared__ float As[BK][BM];
    __shared__ float Bs[BK][BN];

    const int tid = threadIdx.x;
    const int m0 = blockIdx.y * BM;
    const int n0 = blockIdx.x * BN;
    const int tr = tid >> 4;      // 0..15
    const int tc = tid & 15;      // 0..15

    float acc[8][8];
    #pragma unroll
    for (int i = 0; i < 8; i++)
        #pragma unroll
        for (int j = 0; j < 8; j++) acc[i][j] = 0.f;

    for (int k0 = 0; k0 < K; k0 += BK) {
        // load A tile (128 rows x 16 k), store transposed [k][m]
        #pragma unroll
        for (int i = 0; i < 2; i++) {
            int f   = tid + i * 256;        // 0..511 float4 slots
            int row = f >> 2;               // 4 float4 per row
            int c4  = (f & 3) * 4;
            float4 v = *(const float4*)(A + (size_t)(m0 + row) * K + k0 + c4);
            As[c4 + 0][row] = v.x; As[c4 + 1][row] = v.y;
            As[c4 + 2][row] = v.z; As[c4 + 3][row] = v.w;
        }
        // load B tile (128 n-rows x 16 k), store transposed [k][n]
        #pragma unroll
        for (int i = 0; i < 2; i++) {
            int f   = tid + i * 256;
            int row = f >> 2;
            int c4  = (f & 3) * 4;
            float4 v = *(const float4*)(Bw + (size_t)(n0 + row) * K + k0 + c4);
            Bs[c4 + 0][row] = v.x; Bs[c4 + 1][row] = v.y;
            Bs[c4 + 2][row] = v.z; Bs[c4 + 3][row] = v.w;
        }
        __syncthreads();

        #pragma unroll
        for (int kk = 0; kk < BK; kk++) {
            float a[8], b[8];
            #pragma unroll
            for (int i = 0; i < 8; i++) a[i] = As[kk][tr * 8 + i];
            #pragma unroll
            for (int j = 0; j < 8; j++) b[j] = Bs[kk][tc * 8 + j];
            #pragma unroll
            for (int i = 0; i < 8; i++)
                #pragma unroll
                for (int j = 0; j < 8; j++)
                    acc[i][j] += a[i] * b[j];
        }
        __syncthreads();
    }

    // epilogue: add bias, store
    #pragma unroll
    for (int i = 0; i < 8; i++) {
        int m = m0 + tr * 8 + i;
        #pragma unroll
        for (int j = 0; j < 8; j += 4) {
            int n = n0 + tc * 8 + j;
            float4 v;
            v.x = acc[i][j + 0] + bias[n + 0];
            v.y = acc[i][j + 1] + bias[n + 1];
            v.z = acc[i][j + 2] + bias[n + 2];
            v.w = acc[i][j + 3] + bias[n + 3];
            *(float4*)(C + (size_t)m * N + n) = v;
        }
    }
}

// ---------------------------------------------------------------------------
// Window attention: one block = (window, head). 64 threads, one per query row.
// Q row / scores / output row live in registers; K,V broadcast from smem.
// ---------------------------------------------------------------------------
__global__ __launch_bounds__(64)
void win_attn_kernel(const float* __restrict__ bias_table)
{
    __shared__ float Qs[WS][HEAD_DIM];
    __shared__ float Ks[WS][HEAD_DIM];
    __shared__ float Vs[WS][HEAD_DIM];
    __shared__ float bias_s[225];     // (2*8-1)*(2*8-1)

    const int t    = threadIdx.x;             // query row 0..63
    const int head = blockIdx.y;
    const int bi   = blockIdx.x >> 10;        // 1024 windows per image
    const int wid  = blockIdx.x & 1023;
    const int wy   = wid >> 5, wx = wid & 31;

    const int r = t >> 3, c = t & 7;
    const int gy = wy * 8 + r, gx = wx * 8 + c;
    const size_t tok = (size_t)bi * TOKENS + (size_t)gy * IMG + gx;
    const float* base = g_qkv + tok * QKV_DIM + head * HEAD_DIM;

    #pragma unroll
    for (int d = 0; d < HEAD_DIM; d += 4) {
        *(float4*)&Qs[t][d] = *(const float4*)(base + d);
        *(float4*)&Ks[t][d] = *(const float4*)(base + C_DIM + d);
        *(float4*)&Vs[t][d] = *(const float4*)(base + 2 * C_DIM + d);
    }
    for (int i = t; i < 225; i += 64)
        bias_s[i] = bias_table[i * N_HEADS + head];
    __syncthreads();

    float q[HEAD_DIM];
    #pragma unroll
    for (int d = 0; d < HEAD_DIM; d++) q[d] = Qs[t][d];

    const float scale = 0.17677669529663689f;   // 1/sqrt(32)
    float s[WS];
    #pragma unroll
    for (int k = 0; k < WS; k++) {
        float dot = 0.f;
        #pragma unroll
        for (int d = 0; d < HEAD_DIM; d++) dot += q[d] * Ks[k][d];
        int ki = k >> 3, kj = k & 7;
        s[k] = dot * scale + bias_s[(r - ki + 7) * 15 + (c - kj + 7)];
    }

    float m = -1e30f;
    #pragma unroll
    for (int k = 0; k < WS; k++) m = fmaxf(m, s[k]);
    float sum = 0.f;
    #pragma unroll
    for (int k = 0; k < WS; k++) { s[k] = __expf(s[k] - m); sum += s[k]; }
    const float inv = 1.f / sum;

    float y[HEAD_DIM];
    #pragma unroll
    for (int d = 0; d < HEAD_DIM; d++) y[d] = 0.f;
    #pragma unroll
    for (int k = 0; k < WS; k++) {
        float p = s[k];
        #pragma unroll
        for (int d = 0; d < HEAD_DIM; d++) y[d] += p * Vs[k][d];
    }

    float* outp = g_y + tok * C_DIM + head * HEAD_DIM;
    #pragma unroll
    for (int d = 0; d < HEAD_DIM; d += 4) {
        float4 v;
        v.x = y[d + 0] * inv; v.y = y[d + 1] * inv;
        v.z = y[d + 2] * inv; v.w = y[d + 3] * inv;
        *(float4*)(outp + d) = v;
    }
}

// ---------------------------------------------------------------------------
extern "C" void kernel_launch(void* const* d_in, const int* in_sizes, int n_in,
                              void* d_out, int out_size)
{
    // identify inputs by element count (robust to h/w scalar placement)
    const float *x = nullptr, *wqkv_w = nullptr, *wqkv_b = nullptr;
    const float *wp_w = nullptr, *wp_b = nullptr, *bias_table = nullptr;
    long long x_elems = 0;
    for (int i = 0; i < n_in; i++) {
        long long sz = in_sizes[i];
        if      (sz == 768LL * 256)  wqkv_w = (const float*)d_in[i];
        else if (sz == 768)          wqkv_b = (const float*)d_in[i];
        else if (sz == 256LL * 256)  wp_w   = (const float*)d_in[i];
        else if (sz == 256)          wp_b   = (const float*)d_in[i];
        else if (sz == 225LL * 8)    bias_table = (const float*)d_in[i];
        else if (sz > 1000000)       { x = (const float*)d_in[i]; x_elems = sz; }
    }

    const int B = (int)(x_elems / ((long long)TOKENS * C_DIM));   // = 2
    const int M = B * TOKENS;

    float* qkv_ptr; cudaGetSymbolAddress((void**)&qkv_ptr, g_qkv);
    float* y_ptr;   cudaGetSymbolAddress((void**)&y_ptr,   g_y);

    // 1) QKV projection
    {
        dim3 grid(QKV_DIM / 128, M / 128);
        sgemm_bias_kernel<<<grid, 256>>>(x, wqkv_w, wqkv_b, qkv_ptr,
                                         M, QKV_DIM, C_DIM);
    }
    // 2) window attention
    {
        dim3 grid(B * 1024, N_HEADS);
        win_attn_kernel<<<grid, 64>>>(bias_table);
    }
    // 3) output projection
    {
        dim3 grid(C_DIM / 128, M / 128);
        sgemm_bias_kernel<<<grid, 256>>>(y_ptr, wp_w, wp_b, (float*)d_out,
                                         M, C_DIM, C_DIM);
    }
}

// round 2
// speedup vs baseline: 2.0971x; 2.0971x over previous
#include <cuda_runtime.h>
#include <cstdint>

// ---------------------------------------------------------------------------
// SpatialWindowSelfAttention (Swin window MHSA), sm_103a — Round 2
//   1) TF32 tensor-core GEMM  qkv = x @ Wqkv^T + b   (M=131072,N=768,K=256)
//   2) window attention (fp32, unchanged from R1)
//   3) TF32 tensor-core GEMM  out = y @ Wp^T + b     (M=131072,N=256,K=256)
// ---------------------------------------------------------------------------

#define C_DIM    256
#define QKV_DIM  768
#define N_HEADS  8
#define HEAD_DIM 32
#define IMG      256
#define TOKENS   (IMG * IMG)         // 65536
#define WS       64
#define MAX_B    2

__device__ float g_qkv[MAX_B * TOKENS * QKV_DIM];
__device__ float g_y  [MAX_B * TOKENS * C_DIM];

// ---------------------------------------------------------------------------
// TF32 helpers
// ---------------------------------------------------------------------------
__device__ __forceinline__ uint32_t to_tf32(float x) {
    uint32_t r;
    asm("cvt.rna.tf32.f32 %0, %1;" : "=r"(r) : "f"(x));
    return r;
}

__device__ __forceinline__ void mma_tf32(float* d, const uint32_t* a, const uint32_t* b) {
    asm volatile(
        "mma.sync.aligned.m16n8k8.row.col.f32.tf32.tf32.f32 "
        "{%0,%1,%2,%3}, {%4,%5,%6,%7}, {%8,%9}, {%0,%1,%2,%3};\n"
        : "+f"(d[0]), "+f"(d[1]), "+f"(d[2]), "+f"(d[3])
        : "r"(a[0]), "r"(a[1]), "r"(a[2]), "r"(a[3]),
          "r"(b[0]), "r"(b[1]));
}

// ---------------------------------------------------------------------------
// TF32 GEMM: C[M,N] = A[M,K] @ Bw[N,K]^T + bias[N]
// BM=BN=128, BK=32. 256 threads = 8 warps (4 along M x 2 along N).
// Warp tile 32x64 -> 2 m-frags x 8 n-frags of m16n8k8.
// Smem tiles stored [row][k] with stride 36 (36 % 32 == 4) so fragment
// loads hit bank (4*g + t) -> all 32 banks, conflict-free.
// ---------------------------------------------------------------------------
__global__ __launch_bounds__(256)
void tf32_gemm_bias_kernel(const float* __restrict__ A,
                           const float* __restrict__ Bw,
                           const float* __restrict__ bias,
                           float* __restrict__ C,
                           int M, int N, int K)
{
    constexpr int BM = 128, BN = 128, BK = 32, LDS_S = 36;
    __shared__ uint32_t As[BM][LDS_S];
    __shared__ uint32_t Bs[BN][LDS_S];

    const int tid  = threadIdx.x;
    const int lane = tid & 31;
    const int wid  = tid >> 5;
    const int wm   = (wid & 3) * 32;     // warp m offset within block
    const int wn   = (wid >> 2) * 64;    // warp n offset within block
    const int m0   = blockIdx.y * BM;
    const int n0   = blockIdx.x * BN;
    const int t    = lane & 3;           // threadID_in_group
    const int g    = lane >> 2;          // groupID

    float acc[2][8][4];
    #pragma unroll
    for (int i = 0; i < 2; i++)
        #pragma unroll
        for (int j = 0; j < 8; j++)
            #pragma unroll
            for (int r = 0; r < 4; r++) acc[i][j][r] = 0.f;

    for (int k0 = 0; k0 < K; k0 += BK) {
        // load A tile: 128 rows x 32 k = 1024 float4, 4 per thread
        #pragma unroll
        for (int i = 0; i < 4; i++) {
            int f   = tid + i * 256;
            int row = f >> 3;            // 8 float4 per row
            int kc  = (f & 7) * 4;
            float4 v = *(const float4*)(A + (size_t)(m0 + row) * K + k0 + kc);
            As[row][kc + 0] = to_tf32(v.x);
            As[row][kc + 1] = to_tf32(v.y);
            As[row][kc + 2] = to_tf32(v.z);
            As[row][kc + 3] = to_tf32(v.w);
        }
        // load B tile: 128 n-rows x 32 k
        #pragma unroll
        for (int i = 0; i < 4; i++) {
            int f   = tid + i * 256;
            int row = f >> 3;
            int kc  = (f & 7) * 4;
            float4 v = *(const float4*)(Bw + (size_t)(n0 + row) * K + k0 + kc);
            Bs[row][kc + 0] = to_tf32(v.x);
            Bs[row][kc + 1] = to_tf32(v.y);
            Bs[row][kc + 2] = to_tf32(v.z);
            Bs[row][kc + 3] = to_tf32(v.w);
        }
        __syncthreads();

        #pragma unroll
        for (int ks = 0; ks < 4; ks++) {
            const int kb = ks * 8;
            uint32_t a[2][4], b[8][2];
            #pragma unroll
            for (int mf = 0; mf < 2; mf++) {
                int r = wm + mf * 16 + g;
                a[mf][0] = As[r    ][kb + t];
                a[mf][1] = As[r + 8][kb + t];
                a[mf][2] = As[r    ][kb + t + 4];
                a[mf][3] = As[r + 8][kb + t + 4];
            }
            #pragma unroll
            for (int nf = 0; nf < 8; nf++) {
                int n = wn + nf * 8 + g;
                b[nf][0] = Bs[n][kb + t];
                b[nf][1] = Bs[n][kb + t + 4];
            }
            #pragma unroll
            for (int mf = 0; mf < 2; mf++)
                #pragma unroll
                for (int nf = 0; nf < 8; nf++)
                    mma_tf32(acc[mf][nf], a[mf], b[nf]);
        }
        __syncthreads();
    }

    // epilogue: bias + store (c0,c1 at cols 2t,2t+1; c2,c3 at row+8)
    #pragma unroll
    for (int mf = 0; mf < 2; mf++) {
        int row = m0 + wm + mf * 16 + g;
        #pragma unroll
        for (int nf = 0; nf < 8; nf++) {
            int col = n0 + wn + nf * 8 + 2 * t;
            float bx = bias[col], by = bias[col + 1];
            float2 v0 = make_float2(acc[mf][nf][0] + bx, acc[mf][nf][1] + by);
            float2 v1 = make_float2(acc[mf][nf][2] + bx, acc[mf][nf][3] + by);
            *(float2*)(C + (size_t)row * N + col)       = v0;
            *(float2*)(C + (size_t)(row + 8) * N + col) = v1;
        }
    }
}

// ---------------------------------------------------------------------------
// Window attention: one block = (window, head). 64 threads, one per query row.
// ---------------------------------------------------------------------------
__global__ __launch_bounds__(64)
void win_attn_kernel(const float* __restrict__ bias_table)
{
    __shared__ float Qs[WS][HEAD_DIM];
    __shared__ float Ks[WS][HEAD_DIM];
    __shared__ float Vs[WS][HEAD_DIM];
    __shared__ float bias_s[225];

    const int t    = threadIdx.x;
    const int head = blockIdx.y;
    const int bi   = blockIdx.x >> 10;
    const int wid  = blockIdx.x & 1023;
    const int wy   = wid >> 5, wx = wid & 31;

    const int r = t >> 3, c = t & 7;
    const int gy = wy * 8 + r, gx = wx * 8 + c;
    const size_t tok = (size_t)bi * TOKENS + (size_t)gy * IMG + gx;
    const float* base = g_qkv + tok * QKV_DIM + head * HEAD_DIM;

    #pragma unroll
    for (int d = 0; d < HEAD_DIM; d += 4) {
        *(float4*)&Qs[t][d] = *(const float4*)(base + d);
        *(float4*)&Ks[t][d] = *(const float4*)(base + C_DIM + d);
        *(float4*)&Vs[t][d] = *(const float4*)(base + 2 * C_DIM + d);
    }
    for (int i = t; i < 225; i += 64)
        bias_s[i] = bias_table[i * N_HEADS + head];
    __syncthreads();

    float q[HEAD_DIM];
    #pragma unroll
    for (int d = 0; d < HEAD_DIM; d++) q[d] = Qs[t][d];

    const float scale = 0.17677669529663689f;
    float s[WS];
    #pragma unroll
    for (int k = 0; k < WS; k++) {
        float dot = 0.f;
        #pragma unroll
        for (int d = 0; d < HEAD_DIM; d++) dot += q[d] * Ks[k][d];
        int ki = k >> 3, kj = k & 7;
        s[k] = dot * scale + bias_s[(r - ki + 7) * 15 + (c - kj + 7)];
    }

    float m = -1e30f;
    #pragma unroll
    for (int k = 0; k < WS; k++) m = fmaxf(m, s[k]);
    float sum = 0.f;
    #pragma unroll
    for (int k = 0; k < WS; k++) { s[k] = __expf(s[k] - m); sum += s[k]; }
    const float inv = 1.f / sum;

    float y[HEAD_DIM];
    #pragma unroll
    for (int d = 0; d < HEAD_DIM; d++) y[d] = 0.f;
    #pragma unroll
    for (int k = 0; k < WS; k++) {
        float p = s[k];
        #pragma unroll
        for (int d = 0; d < HEAD_DIM; d++) y[d] += p * Vs[k][d];
    }

    float* outp = g_y + tok * C_DIM + head * HEAD_DIM;
    #pragma unroll
    for (int d = 0; d < HEAD_DIM; d += 4) {
        float4 v;
        v.x = y[d + 0] * inv; v.y = y[d + 1] * inv;
        v.z = y[d + 2] * inv; v.w = y[d + 3] * inv;
        *(float4*)(outp + d) = v;
    }
}

// ---------------------------------------------------------------------------
extern "C" void kernel_launch(void* const* d_in, const int* in_sizes, int n_in,
                              void* d_out, int out_size)
{
    const float *x = nullptr, *wqkv_w = nullptr, *wqkv_b = nullptr;
    const float *wp_w = nullptr, *wp_b = nullptr, *bias_table = nullptr;
    long long x_elems = 0;
    for (int i = 0; i < n_in; i++) {
        long long sz = in_sizes[i];
        if      (sz == 768LL * 256)  wqkv_w = (const float*)d_in[i];
        else if (sz == 768)          wqkv_b = (const float*)d_in[i];
        else if (sz == 256LL * 256)  wp_w   = (const float*)d_in[i];
        else if (sz == 256)          wp_b   = (const float*)d_in[i];
        else if (sz == 225LL * 8)    bias_table = (const float*)d_in[i];
        else if (sz > 1000000)       { x = (const float*)d_in[i]; x_elems = sz; }
    }

    const int B = (int)(x_elems / ((long long)TOKENS * C_DIM));   // = 2
    const int M = B * TOKENS;

    float* qkv_ptr; cudaGetSymbolAddress((void**)&qkv_ptr, g_qkv);
    float* y_ptr;   cudaGetSymbolAddress((void**)&y_ptr,   g_y);

    // 1) QKV projection (TF32 tensor cores)
    {
        dim3 grid(QKV_DIM / 128, M / 128);
        tf32_gemm_bias_kernel<<<grid, 256>>>(x, wqkv_w, wqkv_b, qkv_ptr,
                                             M, QKV_DIM, C_DIM);
    }
    // 2) window attention
    {
        dim3 grid(B * 1024, N_HEADS);
        win_attn_kernel<<<grid, 64>>>(bias_table);
    }
    // 3) output projection (TF32 tensor cores)
    {
        dim3 grid(C_DIM / 128, M / 128);
        tf32_gemm_bias_kernel<<<grid, 256>>>(y_ptr, wp_w, wp_b, (float*)d_out,
                                             M, C_DIM, C_DIM);
    }
}